// round 16
// baseline (speedup 1.0000x reference)
#include <cuda_runtime.h>
#include <cuda_fp16.h>
#include <cuda.h>
#include <cstdint>

// ============================================================================
// out[b,s,o] = sum_k x[b,s,k] * (centroids[nib(o,k)] * scales[o,k/64])
// B=4 S=2048 K=4096 O=4096.
//
// R16 = R13 GEMM verbatim (TMA-fed 3-stage pipeline, 128-thread CTAs,
// 128x128 tile, 64x64 warp tiles, 2 CTAs/SM, mma.sync fp16/fp32; reissue
// AFTER all ks MMAs -- the consuming MMAs are the completion fence for the
// ldmatrix reads, which R15's early reissue broke) + R15's safe prep widening
// (2 float4/thread, single 16B store).
// ============================================================================

static constexpr int KDIM = 4096, ODIM = 4096;
static constexpr int MDIM = 8192;          // 4*2048

static constexpr int TM = 128, TN = 128, TK = 64;
static constexpr int NCHUNK = KDIM / TK;   // 64
static constexpr int STAGES = 3;
static constexpr int NTHREADS = 128;
static constexpr int STAGE_BYTES = (TM + TN) * TK * 2;   // 32768 (A 16K + B 16K)
static constexpr int SMEM_REQ = STAGES * STAGE_BYTES + 2048;  // mbars + align

// merged prep grid split (conv handles 2 float4 per thread)
static constexpr int CONV_BLOCKS = 16384;   // 8388608 float4 / (256*2)
static constexpr int DEQ_BLOCKS  = 4096;    // 1048576 groups / 256

__device__ __half g_A[(size_t)MDIM * KDIM];   // 64 MiB
__device__ __half g_B[(size_t)ODIM * KDIM];   // 32 MiB

// ---------------------------------------------------------------------------
__device__ __forceinline__ uint32_t smem_u32(const void* p) {
    uint32_t a;
    asm("{ .reg .u64 t; cvta.to.shared.u64 t, %1; cvt.u32.u64 %0, t; }"
        : "=r"(a) : "l"(p));
    return a;
}

__device__ __forceinline__ void ldsm_x4(uint32_t* r, uint32_t addr) {
    asm volatile("ldmatrix.sync.aligned.m8n8.x4.shared.b16 {%0,%1,%2,%3}, [%4];"
                 : "=r"(r[0]), "=r"(r[1]), "=r"(r[2]), "=r"(r[3]) : "r"(addr));
}

__device__ __forceinline__ void mma16816(float* c, const uint32_t* a, const uint32_t* b) {
    asm volatile(
        "mma.sync.aligned.m16n8k16.row.col.f32.f16.f16.f32 "
        "{%0,%1,%2,%3}, {%4,%5,%6,%7}, {%8,%9}, {%0,%1,%2,%3};"
        : "+f"(c[0]), "+f"(c[1]), "+f"(c[2]), "+f"(c[3])
        : "r"(a[0]), "r"(a[1]), "r"(a[2]), "r"(a[3]), "r"(b[0]), "r"(b[1]));
}

// swizzled byte offset within a [rows][64] fp16 tile (128B rows) — identical
// to the TMA SW128 pattern for 128B-wide boxes.
__device__ __forceinline__ uint32_t swz(int r, int kb) {
    return (uint32_t)(r * 128 + (kb ^ ((r & 7) << 4)));
}

#define MBARRIER_INIT(mbar, count) \
    asm volatile("mbarrier.init.shared.b64 [%0], %1;" \
                 :: "r"((uint32_t)(mbar)), "r"((uint32_t)(count)) : "memory")

#define MBARRIER_EXPECT_TX(mbar, bytes) \
    asm volatile("mbarrier.arrive.expect_tx.shared.b64 _, [%0], %1;" \
                 :: "r"((uint32_t)(mbar)), "r"((uint32_t)(bytes)) : "memory")

#define MBARRIER_WAIT_PARITY(mbar_addr, phase_parity) do {                         \
    uint32_t _mbar = (uint32_t)(mbar_addr);                                        \
    uint32_t _par  = (uint32_t)(phase_parity);                                     \
    uint32_t _done;                                                                \
    asm volatile(                                                                  \
        "{\n\t.reg .pred p;\n\t"                                                   \
        "mbarrier.try_wait.parity.acquire.cta.shared::cta.b64 p, [%1], %2;\n\t"    \
        "selp.b32 %0, 1, 0, p;\n\t}"                                               \
        : "=r"(_done) : "r"(_mbar), "r"(_par) : "memory");                         \
    if (!_done) {                                                                  \
        asm volatile(                                                              \
            "{\n\t.reg .pred P1;\n\t"                                              \
            "WAIT_LOOP_%=:\n\t"                                                    \
            "mbarrier.try_wait.parity.acquire.cta.shared::cta.b64 P1, [%0], %1, 0x989680;\n\t" \
            "@P1 bra.uni WAIT_DONE_%=;\n\t"                                        \
            "bra.uni WAIT_LOOP_%=;\n\t"                                            \
            "WAIT_DONE_%=:\n\t}"                                                   \
            :: "r"(_mbar), "r"(_par) : "memory");                                  \
    }                                                                              \
} while (0)

__device__ __forceinline__ void tma2d(uint32_t dst, const CUtensorMap* map,
                                      int cx, int cy, uint32_t mbar) {
    asm volatile(
        "cp.async.bulk.tensor.2d.shared::cta.global.tile.mbarrier::complete_tx::bytes "
        "[%0], [%1, {%2, %3}], [%4];"
        :: "r"(dst), "l"(map), "r"(cx), "r"(cy), "r"(mbar) : "memory");
}

// ---------------------------------------------------------------------------
// Merged prep
// ---------------------------------------------------------------------------
__global__ void k_prep(const float4* __restrict__ x,
                       const uint32_t* __restrict__ wp,
                       const float* __restrict__ cent,
                       const float* __restrict__ scales) {
    if (blockIdx.x < CONV_BLOCKS) {
        // ---- x conversion: two float4 per thread, one 16B store ----
        size_t i = ((size_t)blockIdx.x * blockDim.x + threadIdx.x) * 2;
        float4 v0 = x[i];
        float4 v1 = x[i + 1];
        union { __half2 h2[4]; uint4 u; } o;
        o.h2[0] = __float22half2_rn(make_float2(v0.x, v0.y));
        o.h2[1] = __float22half2_rn(make_float2(v0.z, v0.w));
        o.h2[2] = __float22half2_rn(make_float2(v1.x, v1.y));
        o.h2[3] = __float22half2_rn(make_float2(v1.z, v1.w));
        *reinterpret_cast<uint4*>(g_A + i * 4) = o.u;
    } else {
        __shared__ float sc[16];
        __shared__ int   sfmt;
        if (threadIdx.x < 16) sc[threadIdx.x] = cent[threadIdx.x];
        if (threadIdx.x == 0) {
            int expanded = 1;
            #pragma unroll 1
            for (int i = 0; i < 64; i++)
                if (wp[i] & 0xFFFFFF00u) { expanded = 0; break; }
            sfmt = expanded;
        }
        __syncthreads();

        const int t  = (blockIdx.x - CONV_BLOCKS) * blockDim.x + threadIdx.x;
        const int o  = t >> 8;
        const int jb = (t & 255) * 8;
        const float s = __ldg(scales + o * 64 + (jb >> 5));

        uint32_t w[2];
        if (sfmt) {
            const int32_t* wi = reinterpret_cast<const int32_t*>(wp);
            const size_t j0 = (size_t)t * 8;
            w[0] = w[1] = 0;
            #pragma unroll
            for (int i = 0; i < 4; i++) {
                w[0] |= ((uint32_t)wi[j0 + i]     & 0xFFu) << (8 * i);
                w[1] |= ((uint32_t)wi[j0 + 4 + i] & 0xFFu) << (8 * i);
            }
        } else {
            w[0] = wp[t * 2];
            w[1] = wp[t * 2 + 1];
        }

        union { __half h[16]; uint4 u[2]; } out;
        #pragma unroll
        for (int half = 0; half < 2; half++) {
            const uint32_t word = w[half];
            #pragma unroll
            for (int b = 0; b < 4; b++) {
                const uint32_t byte = (word >> (8 * b)) & 0xFF;
                const int base = half * 8 + 2 * b;
                out.h[base + 0] = __float2half(sc[byte >> 4] * s);  // HIGH nibble first
                out.h[base + 1] = __float2half(sc[byte & 15] * s);
            }
        }
        uint4* dst = reinterpret_cast<uint4*>(g_B + (size_t)o * KDIM + (size_t)jb * 2);
        dst[0] = out.u[0];
        dst[1] = out.u[1];
    }
}

// ---------------------------------------------------------------------------
// GEMM with TMA-fed 3-stage pipeline (R13 structure, proven correct+fastest).
// ---------------------------------------------------------------------------
__global__ void __launch_bounds__(NTHREADS, 2) k_gemm(
    const __grid_constant__ CUtensorMap mapA,
    const __grid_constant__ CUtensorMap mapB,
    float* __restrict__ out)
{
    extern __shared__ char smem[];
    const uint32_t sraw = smem_u32(smem);
    const uint32_t mbar = sraw;                         // 3 mbarriers, 8B each
    const uint32_t sb   = (sraw + 1024u) & ~1023u;      // stages, 1024-aligned

    const int tid  = threadIdx.x;
    const int wid  = tid >> 5;
    const int lane = tid & 31;
    const int m0   = blockIdx.y * TM;
    const int n0   = blockIdx.x * TN;

    const int wm0 = (wid >> 1) * 64;
    const int wn0 = (wid & 1) * 64;

    if (tid == 0) {
        MBARRIER_INIT(mbar + 0, 1);
        MBARRIER_INIT(mbar + 8, 1);
        MBARRIER_INIT(mbar + 16, 1);
    }
    __syncthreads();

    // prologue: fill all 3 stages
    if (tid == 0) {
        #pragma unroll
        for (int s = 0; s < STAGES; s++) {
            MBARRIER_EXPECT_TX(mbar + 8 * s, STAGE_BYTES);
            tma2d(sb + s * STAGE_BYTES,         &mapA, s * TK, m0, mbar + 8 * s);
            tma2d(sb + s * STAGE_BYTES + 16384, &mapB, s * TK, n0, mbar + 8 * s);
        }
    }

    float acc[4][8][4];
    #pragma unroll
    for (int i = 0; i < 4; i++)
        #pragma unroll
        for (int j = 0; j < 8; j++)
            #pragma unroll
            for (int k = 0; k < 4; k++) acc[i][j][k] = 0.f;

    const int laneA_r  = lane & 15;
    const int laneA_kb = (lane >> 4) << 4;
    const int laneB_r  = ((lane & 16) >> 1) + (lane & 7);
    const int laneB_kb = ((lane >> 3) & 1) << 4;

    for (int kc = 0; kc < NCHUNK; kc++) {
        const int s = kc % STAGES;
        MBARRIER_WAIT_PARITY(mbar + 8 * s, (uint32_t)((kc / STAGES) & 1));

        const uint32_t aS = sb + s * STAGE_BYTES;
        const uint32_t bS = aS + 16384;

        #pragma unroll
        for (int ks = 0; ks < 4; ks++) {
            const int kb = ks * 32;
            uint32_t a[4][4];
            #pragma unroll
            for (int tm = 0; tm < 4; tm++) {
                const int r = wm0 + tm * 16 + laneA_r;
                ldsm_x4(a[tm], aS + swz(r, kb + laneA_kb));
            }
            uint32_t b[8][2];
            #pragma unroll
            for (int j = 0; j < 4; j++) {
                const int r = wn0 + j * 16 + laneB_r;
                uint32_t t[4];
                ldsm_x4(t, bS + swz(r, kb + laneB_kb));
                b[2*j][0] = t[0];   b[2*j][1] = t[1];
                b[2*j+1][0] = t[2]; b[2*j+1][1] = t[3];
            }
            #pragma unroll
            for (int tm = 0; tm < 4; tm++)
                #pragma unroll
                for (int tn = 0; tn < 8; tn++)
                    mma16816(acc[tm][tn], a[tm], b[tn]);
        }

        __syncthreads();   // all warps done reading stage s (MMAs consumed LDSMs)
        if (tid == 0 && kc + STAGES < NCHUNK) {
            MBARRIER_EXPECT_TX(mbar + 8 * s, STAGE_BYTES);
            tma2d(aS, &mapA, (kc + STAGES) * TK, m0, mbar + 8 * s);
            tma2d(bS, &mapB, (kc + STAGES) * TK, n0, mbar + 8 * s);
        }
    }

    const int mrow = lane >> 2;
    const int ncol = (lane & 3) * 2;
    #pragma unroll
    for (int tm = 0; tm < 4; tm++) {
        #pragma unroll
        for (int tn = 0; tn < 8; tn++) {
            const int m = m0 + wm0 + tm * 16 + mrow;
            const int n = n0 + wn0 + tn * 8 + ncol;
            float2* p0 = reinterpret_cast<float2*>(out + (size_t)m * ODIM + n);
            float2* p1 = reinterpret_cast<float2*>(out + (size_t)(m + 8) * ODIM + n);
            *p0 = make_float2(acc[tm][tn][0], acc[tm][tn][1]);
            *p1 = make_float2(acc[tm][tn][2], acc[tm][tn][3]);
        }
    }
}

// ---------------------------------------------------------------------------
typedef CUresult (*EncodeFn)(
    CUtensorMap*, CUtensorMapDataType, cuuint32_t, void*,
    const cuuint64_t*, const cuuint64_t*, const cuuint32_t*, const cuuint32_t*,
    CUtensorMapInterleave, CUtensorMapSwizzle, CUtensorMapL2promotion,
    CUtensorMapFloatOOBfill);

static void make_map(EncodeFn enc, CUtensorMap* map, void* base,
                     uint64_t rows, uint64_t cols) {
    cuuint64_t dims[2]    = { cols, rows };          // innermost first
    cuuint64_t strides[1] = { cols * 2 };            // row pitch in bytes
    cuuint32_t box[2]     = { (cuuint32_t)TK, 128 }; // 64 fp16 = 128B (SW128)
    cuuint32_t estr[2]    = { 1, 1 };
    enc(map, CU_TENSOR_MAP_DATA_TYPE_FLOAT16, 2, base, dims, strides, box, estr,
        CU_TENSOR_MAP_INTERLEAVE_NONE, CU_TENSOR_MAP_SWIZZLE_128B,
        CU_TENSOR_MAP_L2_PROMOTION_L2_128B, CU_TENSOR_MAP_FLOAT_OOB_FILL_NONE);
}

extern "C" void kernel_launch(void* const* d_in, const int* in_sizes, int n_in,
                              void* d_out, int out_size) {
    (void)out_size;
    const float*    x      = nullptr;
    const uint32_t* wp     = nullptr;
    const float*    cent   = nullptr;
    const float*    scales = nullptr;

    for (int i = 0; i < n_in; i++) {
        switch (in_sizes[i]) {
            case 16:        cent   = (const float*)d_in[i];    break;
            case 262144:    scales = (const float*)d_in[i];    break;
            case 33554432:  x      = (const float*)d_in[i];    break;
            default:        wp     = (const uint32_t*)d_in[i]; break;  // 8388608
        }
    }
    float* outp = (float*)d_out;

    k_prep<<<CONV_BLOCKS + DEQ_BLOCKS, 256>>>(
        reinterpret_cast<const float4*>(x), wp, cent, scales);

    // tensor maps (host-side; runs at capture time, not replay)
    void* fn = nullptr;
    cudaDriverEntryPointQueryResult qr;
    cudaGetDriverEntryPoint("cuTensorMapEncodeTiled", &fn,
                            cudaEnableDefault, &qr);
    EncodeFn enc = (EncodeFn)fn;

    void *pA = nullptr, *pB = nullptr;
    cudaGetSymbolAddress(&pA, g_A);
    cudaGetSymbolAddress(&pB, g_B);

    CUtensorMap mapA, mapB;
    make_map(enc, &mapA, pA, MDIM, KDIM);
    make_map(enc, &mapB, pB, ODIM, KDIM);

    cudaFuncSetAttribute(k_gemm, cudaFuncAttributeMaxDynamicSharedMemorySize,
                         SMEM_REQ);
    k_gemm<<<dim3(ODIM / TN, MDIM / TM), NTHREADS, SMEM_REQ>>>(mapA, mapB, outp);
}

// round 17
// speedup vs baseline: 1.5241x; 1.5241x over previous
#include <cuda_runtime.h>
#include <cuda_fp16.h>
#include <cuda.h>
#include <cstdint>

// ============================================================================
// out[b,s,o] = sum_k x[b,s,k] * (centroids[nib(o,k)] * scales[o,k/64])
// B=4 S=2048 K=4096 O=4096.
//
// R17 = R16 resubmitted verbatim. R16's 874us measurement is a clock-state
// outlier: its GEMM is byte-identical to R13's (520.8us) yet showed the SAME
// pipe profile (tensor 87.5% vs 87.0%) at 1.57x the duration, with HBM GB/s
// scaled by the same 1.59x factor -> uniformly lower SM clock, not a code
// regression. Re-bench the identical kernel to re-anchor.
//
// Content: R13 GEMM (TMA-fed 3-stage pipeline, 128-thread CTAs, 128x128 tile,
// 64x64 warp tiles, 2 CTAs/SM, mma.sync fp16/fp32; TMA reissue only AFTER the
// consuming MMAs fence the ldmatrix reads) + widened conv prep (2 float4 ->
// one 16B store per thread).
// ============================================================================

static constexpr int KDIM = 4096, ODIM = 4096;
static constexpr int MDIM = 8192;          // 4*2048

static constexpr int TM = 128, TN = 128, TK = 64;
static constexpr int NCHUNK = KDIM / TK;   // 64
static constexpr int STAGES = 3;
static constexpr int NTHREADS = 128;
static constexpr int STAGE_BYTES = (TM + TN) * TK * 2;   // 32768 (A 16K + B 16K)
static constexpr int SMEM_REQ = STAGES * STAGE_BYTES + 2048;  // mbars + align

// merged prep grid split (conv handles 2 float4 per thread)
static constexpr int CONV_BLOCKS = 16384;   // 8388608 float4 / (256*2)
static constexpr int DEQ_BLOCKS  = 4096;    // 1048576 groups / 256

__device__ __half g_A[(size_t)MDIM * KDIM];   // 64 MiB
__device__ __half g_B[(size_t)ODIM * KDIM];   // 32 MiB

// ---------------------------------------------------------------------------
__device__ __forceinline__ uint32_t smem_u32(const void* p) {
    uint32_t a;
    asm("{ .reg .u64 t; cvta.to.shared.u64 t, %1; cvt.u32.u64 %0, t; }"
        : "=r"(a) : "l"(p));
    return a;
}

__device__ __forceinline__ void ldsm_x4(uint32_t* r, uint32_t addr) {
    asm volatile("ldmatrix.sync.aligned.m8n8.x4.shared.b16 {%0,%1,%2,%3}, [%4];"
                 : "=r"(r[0]), "=r"(r[1]), "=r"(r[2]), "=r"(r[3]) : "r"(addr));
}

__device__ __forceinline__ void mma16816(float* c, const uint32_t* a, const uint32_t* b) {
    asm volatile(
        "mma.sync.aligned.m16n8k16.row.col.f32.f16.f16.f32 "
        "{%0,%1,%2,%3}, {%4,%5,%6,%7}, {%8,%9}, {%0,%1,%2,%3};"
        : "+f"(c[0]), "+f"(c[1]), "+f"(c[2]), "+f"(c[3])
        : "r"(a[0]), "r"(a[1]), "r"(a[2]), "r"(a[3]), "r"(b[0]), "r"(b[1]));
}

// swizzled byte offset within a [rows][64] fp16 tile (128B rows) — identical
// to the TMA SW128 pattern for 128B-wide boxes.
__device__ __forceinline__ uint32_t swz(int r, int kb) {
    return (uint32_t)(r * 128 + (kb ^ ((r & 7) << 4)));
}

#define MBARRIER_INIT(mbar, count) \
    asm volatile("mbarrier.init.shared.b64 [%0], %1;" \
                 :: "r"((uint32_t)(mbar)), "r"((uint32_t)(count)) : "memory")

#define MBARRIER_EXPECT_TX(mbar, bytes) \
    asm volatile("mbarrier.arrive.expect_tx.shared.b64 _, [%0], %1;" \
                 :: "r"((uint32_t)(mbar)), "r"((uint32_t)(bytes)) : "memory")

#define MBARRIER_WAIT_PARITY(mbar_addr, phase_parity) do {                         \
    uint32_t _mbar = (uint32_t)(mbar_addr);                                        \
    uint32_t _par  = (uint32_t)(phase_parity);                                     \
    uint32_t _done;                                                                \
    asm volatile(                                                                  \
        "{\n\t.reg .pred p;\n\t"                                                   \
        "mbarrier.try_wait.parity.acquire.cta.shared::cta.b64 p, [%1], %2;\n\t"    \
        "selp.b32 %0, 1, 0, p;\n\t}"                                               \
        : "=r"(_done) : "r"(_mbar), "r"(_par) : "memory");                         \
    if (!_done) {                                                                  \
        asm volatile(                                                              \
            "{\n\t.reg .pred P1;\n\t"                                              \
            "WAIT_LOOP_%=:\n\t"                                                    \
            "mbarrier.try_wait.parity.acquire.cta.shared::cta.b64 P1, [%0], %1, 0x989680;\n\t" \
            "@P1 bra.uni WAIT_DONE_%=;\n\t"                                        \
            "bra.uni WAIT_LOOP_%=;\n\t"                                            \
            "WAIT_DONE_%=:\n\t}"                                                   \
            :: "r"(_mbar), "r"(_par) : "memory");                                  \
    }                                                                              \
} while (0)

__device__ __forceinline__ void tma2d(uint32_t dst, const CUtensorMap* map,
                                      int cx, int cy, uint32_t mbar) {
    asm volatile(
        "cp.async.bulk.tensor.2d.shared::cta.global.tile.mbarrier::complete_tx::bytes "
        "[%0], [%1, {%2, %3}], [%4];"
        :: "r"(dst), "l"(map), "r"(cx), "r"(cy), "r"(mbar) : "memory");
}

// ---------------------------------------------------------------------------
// Merged prep
// ---------------------------------------------------------------------------
__global__ void k_prep(const float4* __restrict__ x,
                       const uint32_t* __restrict__ wp,
                       const float* __restrict__ cent,
                       const float* __restrict__ scales) {
    if (blockIdx.x < CONV_BLOCKS) {
        // ---- x conversion: two float4 per thread, one 16B store ----
        size_t i = ((size_t)blockIdx.x * blockDim.x + threadIdx.x) * 2;
        float4 v0 = x[i];
        float4 v1 = x[i + 1];
        union { __half2 h2[4]; uint4 u; } o;
        o.h2[0] = __float22half2_rn(make_float2(v0.x, v0.y));
        o.h2[1] = __float22half2_rn(make_float2(v0.z, v0.w));
        o.h2[2] = __float22half2_rn(make_float2(v1.x, v1.y));
        o.h2[3] = __float22half2_rn(make_float2(v1.z, v1.w));
        *reinterpret_cast<uint4*>(g_A + i * 4) = o.u;
    } else {
        __shared__ float sc[16];
        __shared__ int   sfmt;
        if (threadIdx.x < 16) sc[threadIdx.x] = cent[threadIdx.x];
        if (threadIdx.x == 0) {
            int expanded = 1;
            #pragma unroll 1
            for (int i = 0; i < 64; i++)
                if (wp[i] & 0xFFFFFF00u) { expanded = 0; break; }
            sfmt = expanded;
        }
        __syncthreads();

        const int t  = (blockIdx.x - CONV_BLOCKS) * blockDim.x + threadIdx.x;
        const int o  = t >> 8;
        const int jb = (t & 255) * 8;
        const float s = __ldg(scales + o * 64 + (jb >> 5));

        uint32_t w[2];
        if (sfmt) {
            const int32_t* wi = reinterpret_cast<const int32_t*>(wp);
            const size_t j0 = (size_t)t * 8;
            w[0] = w[1] = 0;
            #pragma unroll
            for (int i = 0; i < 4; i++) {
                w[0] |= ((uint32_t)wi[j0 + i]     & 0xFFu) << (8 * i);
                w[1] |= ((uint32_t)wi[j0 + 4 + i] & 0xFFu) << (8 * i);
            }
        } else {
            w[0] = wp[t * 2];
            w[1] = wp[t * 2 + 1];
        }

        union { __half h[16]; uint4 u[2]; } out;
        #pragma unroll
        for (int half = 0; half < 2; half++) {
            const uint32_t word = w[half];
            #pragma unroll
            for (int b = 0; b < 4; b++) {
                const uint32_t byte = (word >> (8 * b)) & 0xFF;
                const int base = half * 8 + 2 * b;
                out.h[base + 0] = __float2half(sc[byte >> 4] * s);  // HIGH nibble first
                out.h[base + 1] = __float2half(sc[byte & 15] * s);
            }
        }
        uint4* dst = reinterpret_cast<uint4*>(g_B + (size_t)o * KDIM + (size_t)jb * 2);
        dst[0] = out.u[0];
        dst[1] = out.u[1];
    }
}

// ---------------------------------------------------------------------------
// GEMM with TMA-fed 3-stage pipeline (R13 structure, proven correct+fastest).
// ---------------------------------------------------------------------------
__global__ void __launch_bounds__(NTHREADS, 2) k_gemm(
    const __grid_constant__ CUtensorMap mapA,
    const __grid_constant__ CUtensorMap mapB,
    float* __restrict__ out)
{
    extern __shared__ char smem[];
    const uint32_t sraw = smem_u32(smem);
    const uint32_t mbar = sraw;                         // 3 mbarriers, 8B each
    const uint32_t sb   = (sraw + 1024u) & ~1023u;      // stages, 1024-aligned

    const int tid  = threadIdx.x;
    const int wid  = tid >> 5;
    const int lane = tid & 31;
    const int m0   = blockIdx.y * TM;
    const int n0   = blockIdx.x * TN;

    const int wm0 = (wid >> 1) * 64;
    const int wn0 = (wid & 1) * 64;

    if (tid == 0) {
        MBARRIER_INIT(mbar + 0, 1);
        MBARRIER_INIT(mbar + 8, 1);
        MBARRIER_INIT(mbar + 16, 1);
    }
    __syncthreads();

    // prologue: fill all 3 stages
    if (tid == 0) {
        #pragma unroll
        for (int s = 0; s < STAGES; s++) {
            MBARRIER_EXPECT_TX(mbar + 8 * s, STAGE_BYTES);
            tma2d(sb + s * STAGE_BYTES,         &mapA, s * TK, m0, mbar + 8 * s);
            tma2d(sb + s * STAGE_BYTES + 16384, &mapB, s * TK, n0, mbar + 8 * s);
        }
    }

    float acc[4][8][4];
    #pragma unroll
    for (int i = 0; i < 4; i++)
        #pragma unroll
        for (int j = 0; j < 8; j++)
            #pragma unroll
            for (int k = 0; k < 4; k++) acc[i][j][k] = 0.f;

    const int laneA_r  = lane & 15;
    const int laneA_kb = (lane >> 4) << 4;
    const int laneB_r  = ((lane & 16) >> 1) + (lane & 7);
    const int laneB_kb = ((lane >> 3) & 1) << 4;

    for (int kc = 0; kc < NCHUNK; kc++) {
        const int s = kc % STAGES;
        MBARRIER_WAIT_PARITY(mbar + 8 * s, (uint32_t)((kc / STAGES) & 1));

        const uint32_t aS = sb + s * STAGE_BYTES;
        const uint32_t bS = aS + 16384;

        #pragma unroll
        for (int ks = 0; ks < 4; ks++) {
            const int kb = ks * 32;
            uint32_t a[4][4];
            #pragma unroll
            for (int tm = 0; tm < 4; tm++) {
                const int r = wm0 + tm * 16 + laneA_r;
                ldsm_x4(a[tm], aS + swz(r, kb + laneA_kb));
            }
            uint32_t b[8][2];
            #pragma unroll
            for (int j = 0; j < 4; j++) {
                const int r = wn0 + j * 16 + laneB_r;
                uint32_t t[4];
                ldsm_x4(t, bS + swz(r, kb + laneB_kb));
                b[2*j][0] = t[0];   b[2*j][1] = t[1];
                b[2*j+1][0] = t[2]; b[2*j+1][1] = t[3];
            }
            #pragma unroll
            for (int tm = 0; tm < 4; tm++)
                #pragma unroll
                for (int tn = 0; tn < 8; tn++)
                    mma16816(acc[tm][tn], a[tm], b[tn]);
        }

        __syncthreads();   // all warps done reading stage s (MMAs consumed LDSMs)
        if (tid == 0 && kc + STAGES < NCHUNK) {
            MBARRIER_EXPECT_TX(mbar + 8 * s, STAGE_BYTES);
            tma2d(aS, &mapA, (kc + STAGES) * TK, m0, mbar + 8 * s);
            tma2d(bS, &mapB, (kc + STAGES) * TK, n0, mbar + 8 * s);
        }
    }

    const int mrow = lane >> 2;
    const int ncol = (lane & 3) * 2;
    #pragma unroll
    for (int tm = 0; tm < 4; tm++) {
        #pragma unroll
        for (int tn = 0; tn < 8; tn++) {
            const int m = m0 + wm0 + tm * 16 + mrow;
            const int n = n0 + wn0 + tn * 8 + ncol;
            float2* p0 = reinterpret_cast<float2*>(out + (size_t)m * ODIM + n);
            float2* p1 = reinterpret_cast<float2*>(out + (size_t)(m + 8) * ODIM + n);
            *p0 = make_float2(acc[tm][tn][0], acc[tm][tn][1]);
            *p1 = make_float2(acc[tm][tn][2], acc[tm][tn][3]);
        }
    }
}

// ---------------------------------------------------------------------------
typedef CUresult (*EncodeFn)(
    CUtensorMap*, CUtensorMapDataType, cuuint32_t, void*,
    const cuuint64_t*, const cuuint64_t*, const cuuint32_t*, const cuuint32_t*,
    CUtensorMapInterleave, CUtensorMapSwizzle, CUtensorMapL2promotion,
    CUtensorMapFloatOOBfill);

static void make_map(EncodeFn enc, CUtensorMap* map, void* base,
                     uint64_t rows, uint64_t cols) {
    cuuint64_t dims[2]    = { cols, rows };          // innermost first
    cuuint64_t strides[1] = { cols * 2 };            // row pitch in bytes
    cuuint32_t box[2]     = { (cuuint32_t)TK, 128 }; // 64 fp16 = 128B (SW128)
    cuuint32_t estr[2]    = { 1, 1 };
    enc(map, CU_TENSOR_MAP_DATA_TYPE_FLOAT16, 2, base, dims, strides, box, estr,
        CU_TENSOR_MAP_INTERLEAVE_NONE, CU_TENSOR_MAP_SWIZZLE_128B,
        CU_TENSOR_MAP_L2_PROMOTION_L2_128B, CU_TENSOR_MAP_FLOAT_OOB_FILL_NONE);
}

extern "C" void kernel_launch(void* const* d_in, const int* in_sizes, int n_in,
                              void* d_out, int out_size) {
    (void)out_size;
    const float*    x      = nullptr;
    const uint32_t* wp     = nullptr;
    const float*    cent   = nullptr;
    const float*    scales = nullptr;

    for (int i = 0; i < n_in; i++) {
        switch (in_sizes[i]) {
            case 16:        cent   = (const float*)d_in[i];    break;
            case 262144:    scales = (const float*)d_in[i];    break;
            case 33554432:  x      = (const float*)d_in[i];    break;
            default:        wp     = (const uint32_t*)d_in[i]; break;  // 8388608
        }
    }
    float* outp = (float*)d_out;

    k_prep<<<CONV_BLOCKS + DEQ_BLOCKS, 256>>>(
        reinterpret_cast<const float4*>(x), wp, cent, scales);

    // tensor maps (host-side; runs at capture time, not replay)
    void* fn = nullptr;
    cudaDriverEntryPointQueryResult qr;
    cudaGetDriverEntryPoint("cuTensorMapEncodeTiled", &fn,
                            cudaEnableDefault, &qr);
    EncodeFn enc = (EncodeFn)fn;

    void *pA = nullptr, *pB = nullptr;
    cudaGetSymbolAddress(&pA, g_A);
    cudaGetSymbolAddress(&pB, g_B);

    CUtensorMap mapA, mapB;
    make_map(enc, &mapA, pA, MDIM, KDIM);
    make_map(enc, &mapB, pB, ODIM, KDIM);

    cudaFuncSetAttribute(k_gemm, cudaFuncAttributeMaxDynamicSharedMemorySize,
                         SMEM_REQ);
    k_gemm<<<dim3(ODIM / TN, MDIM / TM), NTHREADS, SMEM_REQ>>>(mapA, mapB, outp);
}